// round 3
// baseline (speedup 1.0000x reference)
#include <cuda_runtime.h>
#include <cstdint>
#include <cstring>
#include <vector>
#include <algorithm>

namespace {
constexpr int kN = 8192, kD = 512, kNC = 64, kNR = 5, kRC = kNC * kNR;
constexpr int kTK = 16, kIters = 20;

// ---------------- host-side JAX threefry2x32 ----------------
struct U2 { uint32_t a, b; };
static inline uint32_t rotl32(uint32_t v, int r) { return (v << r) | (v >> (32 - r)); }

static U2 threefry(U2 key, uint32_t x0, uint32_t x1) {
    uint32_t ks0 = key.a, ks1 = key.b, ks2 = key.a ^ key.b ^ 0x1BD11BDAu;
    const int ra[4] = {13, 15, 26, 6}, rb[4] = {17, 29, 16, 24};
    x0 += ks0; x1 += ks1;
    for (int i = 0; i < 4; i++) { x0 += x1; x1 = rotl32(x1, ra[i]); x1 ^= x0; }
    x0 += ks1; x1 += ks2 + 1u;
    for (int i = 0; i < 4; i++) { x0 += x1; x1 = rotl32(x1, rb[i]); x1 ^= x0; }
    x0 += ks2; x1 += ks0 + 2u;
    for (int i = 0; i < 4; i++) { x0 += x1; x1 = rotl32(x1, ra[i]); x1 ^= x0; }
    x0 += ks0; x1 += ks1 + 3u;
    for (int i = 0; i < 4; i++) { x0 += x1; x1 = rotl32(x1, rb[i]); x1 ^= x0; }
    x0 += ks1; x1 += ks2 + 4u;
    for (int i = 0; i < 4; i++) { x0 += x1; x1 = rotl32(x1, ra[i]); x1 ^= x0; }
    x0 += ks2; x1 += ks0 + 5u;
    return {x0, x1};
}

constexpr bool kPartitionable = true;  // modern JAX default; flip if rel_err fails

static void split_keys(U2 key, int n, U2* out) {
    if (kPartitionable) {
        for (int i = 0; i < n; i++) out[i] = threefry(key, 0u, (uint32_t)i);
    } else {
        std::vector<uint32_t> o(2 * n);
        for (int i = 0; i < n; i++) {
            U2 y = threefry(key, (uint32_t)i, (uint32_t)(n + i));
            o[i] = y.a; o[n + i] = y.b;
        }
        for (int j = 0; j < n; j++) out[j] = { o[2 * j], o[2 * j + 1] };
    }
}

static void random_bits32(U2 key, int n, uint32_t* bits) {
    if (kPartitionable) {
        for (int i = 0; i < n; i++) {
            U2 y = threefry(key, 0u, (uint32_t)i);
            bits[i] = y.a ^ y.b;
        }
    } else {
        int h = n / 2;
        for (int i = 0; i < h; i++) {
            U2 y = threefry(key, (uint32_t)i, (uint32_t)(h + i));
            bits[i] = y.a; bits[h + i] = y.b;
        }
    }
}

// choice(key,N,(64,),replace=False) == permutation(key,N)[:64]; _shuffle = 2 rounds
static void compute_init_indices(int out_idx[kRC]) {
    U2 master{0u, 1234u};
    U2 runkeys[kNR];
    split_keys(master, kNR, runkeys);
    std::vector<int> val(kN), tmp(kN);
    std::vector<uint64_t> kv(kN);
    std::vector<uint32_t> bits(kN);
    for (int r = 0; r < kNR; r++) {
        for (int i = 0; i < kN; i++) val[i] = i;
        U2 cur = runkeys[r];
        for (int round = 0; round < 2; round++) {
            U2 nk[2];
            split_keys(cur, 2, nk);
            cur = nk[0];
            random_bits32(nk[1], kN, bits.data());
            for (int i = 0; i < kN; i++)
                kv[i] = ((uint64_t)bits[i] << 32) | (uint32_t)i;   // stable asc sort
            std::sort(kv.begin(), kv.end());
            for (int i = 0; i < kN; i++) tmp[i] = val[(uint32_t)(kv[i] & 0xffffffffu)];
            val.swap(tmp);
        }
        for (int c = 0; c < kNC; c++) out_idx[r * kNC + c] = val[c];
    }
}
} // namespace

// ---------------- device scratch ----------------
__device__ float g_cent[kRC * kD];
__device__ float g_cnorm[kRC];
__device__ int   g_labels[kNR * kN];
__device__ int   g_knn[kN * kTK];

struct IdxArr { int v[kRC]; };

// ---------------- kernel 1: sim GEMM (NT, fp32, 128x128x16) ----------------
__global__ void __launch_bounds__(256) gemm_sim_kernel(
    const float* __restrict__ A, const float* __restrict__ B, float* __restrict__ C)
{
    __shared__ __align__(16) float As[16][132];
    __shared__ __align__(16) float Bs[16][132];
    const int m0 = blockIdx.y * 128, n0 = blockIdx.x * 128;
    const int tid = threadIdx.x;
    const int tx = tid & 15, ty = tid >> 4;
    const int lr = tid >> 2, lc = (tid & 3) << 2;

    float acc[8][8];
#pragma unroll
    for (int i = 0; i < 8; i++)
#pragma unroll
        for (int j = 0; j < 8; j++) acc[i][j] = 0.f;

    for (int k0 = 0; k0 < kD; k0 += 16) {
#pragma unroll
        for (int p = 0; p < 2; p++) {
            float4 v = *reinterpret_cast<const float4*>(&A[(size_t)(m0 + lr + p * 64) * kD + k0 + lc]);
            As[lc + 0][lr + p * 64] = v.x; As[lc + 1][lr + p * 64] = v.y;
            As[lc + 2][lr + p * 64] = v.z; As[lc + 3][lr + p * 64] = v.w;
            float4 w = *reinterpret_cast<const float4*>(&B[(size_t)(n0 + lr + p * 64) * kD + k0 + lc]);
            Bs[lc + 0][lr + p * 64] = w.x; Bs[lc + 1][lr + p * 64] = w.y;
            Bs[lc + 2][lr + p * 64] = w.z; Bs[lc + 3][lr + p * 64] = w.w;
        }
        __syncthreads();
#pragma unroll
        for (int k = 0; k < 16; k++) {
            float4 a0 = *reinterpret_cast<const float4*>(&As[k][ty * 4]);
            float4 a1 = *reinterpret_cast<const float4*>(&As[k][64 + ty * 4]);
            float4 b0 = *reinterpret_cast<const float4*>(&Bs[k][tx * 4]);
            float4 b1 = *reinterpret_cast<const float4*>(&Bs[k][64 + tx * 4]);
            float av[8] = {a0.x, a0.y, a0.z, a0.w, a1.x, a1.y, a1.z, a1.w};
            float bv[8] = {b0.x, b0.y, b0.z, b0.w, b1.x, b1.y, b1.z, b1.w};
#pragma unroll
            for (int i = 0; i < 8; i++)
#pragma unroll
                for (int j = 0; j < 8; j++)
                    acc[i][j] = fmaf(av[i], bv[j], acc[i][j]);
        }
        __syncthreads();
    }
#pragma unroll
    for (int i = 0; i < 8; i++) {
        int row = m0 + ((i < 4) ? (ty * 4 + i) : (64 + ty * 4 + (i - 4)));
#pragma unroll
        for (int jh = 0; jh < 2; jh++) {
            int col0 = n0 + jh * 64 + tx * 4;
            float4 v;
            v.x = acc[i][jh * 4 + 0]; v.y = acc[i][jh * 4 + 1];
            v.z = acc[i][jh * 4 + 2]; v.w = acc[i][jh * 4 + 3];
            if (row >= col0 && row < col0 + 4) (&v.x)[row - col0] += 10.f;
            *reinterpret_cast<float4*>(&C[(size_t)row * kN + col0]) = v;
        }
    }
}

// ---------------- kernel 2: per-row top-16 ----------------
__device__ __forceinline__ bool beats(float v1, int i1, float v2, int i2) {
    return (v1 > v2) || (v1 == v2 && i1 < i2);
}

__global__ void __launch_bounds__(256) topk_kernel(const float* __restrict__ sim)
{
    __shared__ float sv[256 * 16];
    __shared__ int   si[256 * 16];
    const int row = blockIdx.x, t = threadIdx.x;
    float tv[16]; int ti[16];
#pragma unroll
    for (int k = 0; k < 16; k++) { tv[k] = -3.402823466e38f; ti[k] = 0x7fffffff; }

    const float* rp = sim + (size_t)row * kN;
    for (int j = t; j < kN; j += 256) {
        float v = rp[j];
        if (beats(v, j, tv[15], ti[15])) {
            float cv = v; int ci = j;
#pragma unroll
            for (int k = 0; k < 16; k++) {
                if (beats(cv, ci, tv[k], ti[k])) {
                    float fv = tv[k]; int fi = ti[k];
                    tv[k] = cv; ti[k] = ci; cv = fv; ci = fi;
                }
            }
        }
    }
#pragma unroll
    for (int k = 0; k < 16; k++) { sv[t * 16 + k] = tv[k]; si[t * 16 + k] = ti[k]; }
    __syncthreads();

    for (int s = 128; s >= 1; s >>= 1) {
        if (t < s) {
            float mv[16]; int mi[16];
            int ia = 0, ib = 0;
#pragma unroll
            for (int k = 0; k < 16; k++) {
                float av = sv[t * 16 + ia], bw = sv[(t + s) * 16 + ib];
                int   ai = si[t * 16 + ia], bj = si[(t + s) * 16 + ib];
                bool ta = beats(av, ai, bw, bj);
                mv[k] = ta ? av : bw; mi[k] = ta ? ai : bj;
                if (ta) ia++; else ib++;
            }
#pragma unroll
            for (int k = 0; k < 16; k++) { sv[t * 16 + k] = mv[k]; si[t * 16 + k] = mi[k]; }
        }
        __syncthreads();
    }
    if (t < kTK) g_knn[row * kTK + t] = si[t];
}

// ---------------- kernel 3: gather init centroids ----------------
__global__ void gather_kernel(const float* __restrict__ X, IdxArr ia)
{
    int b = blockIdx.x;
    int src = ia.v[b];
    for (int d = threadIdx.x; d < kD; d += blockDim.x)
        g_cent[(size_t)b * kD + d] = X[(size_t)src * kD + d];
}

// ---------------- kernel 4: centroid norms (initial) ----------------
__global__ void __launch_bounds__(128) cnorm_kernel()
{
    int rc = blockIdx.x;
    float s = 0.f;
    for (int d = threadIdx.x; d < kD; d += 128) {
        float v = g_cent[(size_t)rc * kD + d];
        s = fmaf(v, v, s);
    }
#pragma unroll
    for (int m = 16; m >= 1; m >>= 1) s += __shfl_xor_sync(0xffffffffu, s, m);
    __shared__ float red[4];
    if ((threadIdx.x & 31) == 0) red[threadIdx.x >> 5] = s;
    __syncthreads();
    if (threadIdx.x == 0) g_cnorm[rc] = red[0] + red[1] + red[2] + red[3];
}

// ---------------- kernel 5: fused dist-GEMM + argmin ----------------
__global__ void __launch_bounds__(256) assign_kernel(const float* __restrict__ X)
{
    __shared__ __align__(16) float As[16][132];
    __shared__ __align__(16) float Bs[16][68];
    __shared__ float cns[kNC];

    const int r = blockIdx.y, m0 = blockIdx.x * 128;
    const float* B = g_cent + (size_t)r * kNC * kD;
    const int tid = threadIdx.x;
    const int tx = tid & 15, ty = tid >> 4;
    const int lr = tid >> 2, lc = (tid & 3) << 2;

    if (tid < kNC) cns[tid] = g_cnorm[r * kNC + tid];

    float acc[8][4];
#pragma unroll
    for (int i = 0; i < 8; i++)
#pragma unroll
        for (int j = 0; j < 4; j++) acc[i][j] = 0.f;

    for (int k0 = 0; k0 < kD; k0 += 16) {
#pragma unroll
        for (int p = 0; p < 2; p++) {
            float4 v = *reinterpret_cast<const float4*>(&X[(size_t)(m0 + lr + p * 64) * kD + k0 + lc]);
            As[lc + 0][lr + p * 64] = v.x; As[lc + 1][lr + p * 64] = v.y;
            As[lc + 2][lr + p * 64] = v.z; As[lc + 3][lr + p * 64] = v.w;
        }
        float4 w = *reinterpret_cast<const float4*>(&B[(size_t)lr * kD + k0 + lc]);
        Bs[lc + 0][lr] = w.x; Bs[lc + 1][lr] = w.y;
        Bs[lc + 2][lr] = w.z; Bs[lc + 3][lr] = w.w;
        __syncthreads();
#pragma unroll
        for (int k = 0; k < 16; k++) {
            float4 a0 = *reinterpret_cast<const float4*>(&As[k][ty * 4]);
            float4 a1 = *reinterpret_cast<const float4*>(&As[k][64 + ty * 4]);
            float4 b  = *reinterpret_cast<const float4*>(&Bs[k][tx * 4]);
            float av[8] = {a0.x, a0.y, a0.z, a0.w, a1.x, a1.y, a1.z, a1.w};
            float bv[4] = {b.x, b.y, b.z, b.w};
#pragma unroll
            for (int i = 0; i < 8; i++)
#pragma unroll
                for (int j = 0; j < 4; j++)
                    acc[i][j] = fmaf(av[i], bv[j], acc[i][j]);
        }
        __syncthreads();
    }
#pragma unroll
    for (int i = 0; i < 8; i++) {
        float bv = cns[tx * 4] - 2.f * acc[i][0];
        int   bi = tx * 4;
#pragma unroll
        for (int j = 1; j < 4; j++) {
            float v = cns[tx * 4 + j] - 2.f * acc[i][j];
            if (v < bv) { bv = v; bi = tx * 4 + j; }
        }
#pragma unroll
        for (int m = 1; m < 16; m <<= 1) {   // reduce across tx (lanes 0..15 / 16..31)
            float ov = __shfl_xor_sync(0xffffffffu, bv, m);
            int   oi = __shfl_xor_sync(0xffffffffu, bi, m);
            if (ov < bv || (ov == bv && oi < bi)) { bv = ov; bi = oi; }
        }
        if (tx == 0) {
            int row = m0 + ((i < 4) ? (ty * 4 + i) : (64 + ty * 4 + (i - 4)));
            g_labels[r * kN + row] = bi;
        }
    }
}

// ---------------- kernel 6: deterministic centroid update + norm ----------------
__global__ void __launch_bounds__(512) update_kernel(const float* __restrict__ X)
{
    __shared__ int list[kN];
    __shared__ int wsum[16];
    __shared__ int total_s;
    __shared__ float fred[16];

    const int c = blockIdx.x, r = blockIdx.y;
    const int t = threadIdx.x;            // == dim d (kD == 512)
    const unsigned lane = t & 31;
    const int* lab = g_labels + r * kN;

    // strip-compact matching point indices (ascending order => deterministic sums)
    int mybuf[16];
    int cnt = 0;
    const int p0 = t * 16;
#pragma unroll
    for (int q = 0; q < 16; q++) {
        int p = p0 + q;
        if (lab[p] == c) mybuf[cnt++] = p;
    }
    int incl = cnt;
#pragma unroll
    for (int off = 1; off < 32; off <<= 1) {
        int y = __shfl_up_sync(0xffffffffu, incl, off);
        if (lane >= off) incl += y;
    }
    if (lane == 31) wsum[t >> 5] = incl;
    __syncthreads();
    if (t < 16) {
        int v = wsum[t], s = v;
#pragma unroll
        for (int off = 1; off < 16; off <<= 1) {
            int y = __shfl_up_sync(0x0000ffffu, s, off);
            if ((int)t >= off) s += y;
        }
        wsum[t] = s - v;
    }
    __syncthreads();
    int offset = wsum[t >> 5] + incl - cnt;
    for (int q = 0; q < cnt; q++) list[offset + q] = mybuf[q];
    if (t == 511) total_s = offset + cnt;
    __syncthreads();

    const int total = total_s;
    float sum = 0.f;
    for (int i = 0; i < total; i++) {
        int p = list[i];
        sum += X[(size_t)p * kD + t];
    }
    const int rc = r * kNC + c;
    float oldc = g_cent[(size_t)rc * kD + t];
    float newc = (total > 0) ? (sum / (float)total) : oldc;
    g_cent[(size_t)rc * kD + t] = newc;

    float sq = newc * newc;
#pragma unroll
    for (int m = 16; m >= 1; m >>= 1) sq += __shfl_xor_sync(0xffffffffu, sq, m);
    if (lane == 0) fred[t >> 5] = sq;
    __syncthreads();
    if (t == 0) {
        float s = 0.f;
        for (int w = 0; w < 16; w++) s += fred[w];
        g_cnorm[rc] = s;
    }
}

// ---------------- kernel 7: scatter final output ----------------
__global__ void __launch_bounds__(256) scatter_kernel(
    const float* __restrict__ adj, float* __restrict__ out)
{
    int e = blockIdx.x * blockDim.x + threadIdx.x;   // 0..131071
    int i = e >> 4;
    int j = g_knn[e];
    float v = adj[(size_t)i * kN + j];
    bool m = false;
#pragma unroll
    for (int r = 0; r < kNR; r++)
        m |= (g_labels[r * kN + i] == g_labels[r * kN + j]);
    out[(size_t)i * kN + j] = v + (m ? 1.f : 0.f);
}

// ---------------- launcher ----------------
extern "C" void kernel_launch(void* const* d_in, const int* in_sizes, int n_in,
                              void* d_out, int out_size)
{
    (void)in_sizes; (void)n_in; (void)out_size;
    const float* adj     = (const float*)d_in[0];
    const float* student = (const float*)d_in[1];
    const float* teacher = (const float*)d_in[2];
    float* out = (float*)d_out;

    IdxArr ia;
    compute_init_indices(ia.v);

    dim3 g1(kN / 128, kN / 128);
    gemm_sim_kernel<<<g1, 256>>>(student, teacher, out);   // sim in d_out scratch
    topk_kernel<<<kN, 256>>>(out);                         // -> g_knn
    cudaMemsetAsync(d_out, 0, (size_t)kN * kN * sizeof(float), 0);

    gather_kernel<<<kRC, 128>>>(teacher, ia);
    cnorm_kernel<<<kRC, 128>>>();
    dim3 ga(kN / 128, kNR), gu(kNC, kNR);
    for (int it = 0; it < kIters; it++) {
        assign_kernel<<<ga, 256>>>(teacher);
        update_kernel<<<gu, 512>>>(teacher);
    }
    assign_kernel<<<ga, 256>>>(teacher);                   // final labels

    scatter_kernel<<<kN * kTK / 256, 256>>>(adj, out);
}

// round 4
// speedup vs baseline: 1.0899x; 1.0899x over previous
#include <cuda_runtime.h>
#include <cstdint>
#include <cstring>
#include <vector>
#include <algorithm>

namespace {
constexpr int kN = 8192, kD = 512, kNC = 64, kNR = 5, kRC = kNC * kNR;
constexpr int kTK = 16, kIters = 20;

// ---------------- host-side JAX threefry2x32 ----------------
struct U2 { uint32_t a, b; };
static inline uint32_t rotl32(uint32_t v, int r) { return (v << r) | (v >> (32 - r)); }

static U2 threefry(U2 key, uint32_t x0, uint32_t x1) {
    uint32_t ks0 = key.a, ks1 = key.b, ks2 = key.a ^ key.b ^ 0x1BD11BDAu;
    const int ra[4] = {13, 15, 26, 6}, rb[4] = {17, 29, 16, 24};
    x0 += ks0; x1 += ks1;
    for (int i = 0; i < 4; i++) { x0 += x1; x1 = rotl32(x1, ra[i]); x1 ^= x0; }
    x0 += ks1; x1 += ks2 + 1u;
    for (int i = 0; i < 4; i++) { x0 += x1; x1 = rotl32(x1, rb[i]); x1 ^= x0; }
    x0 += ks2; x1 += ks0 + 2u;
    for (int i = 0; i < 4; i++) { x0 += x1; x1 = rotl32(x1, ra[i]); x1 ^= x0; }
    x0 += ks0; x1 += ks1 + 3u;
    for (int i = 0; i < 4; i++) { x0 += x1; x1 = rotl32(x1, rb[i]); x1 ^= x0; }
    x0 += ks1; x1 += ks2 + 4u;
    for (int i = 0; i < 4; i++) { x0 += x1; x1 = rotl32(x1, ra[i]); x1 ^= x0; }
    x0 += ks2; x1 += ks0 + 5u;
    return {x0, x1};
}

constexpr bool kPartitionable = true;

static void split_keys(U2 key, int n, U2* out) {
    if (kPartitionable) {
        for (int i = 0; i < n; i++) out[i] = threefry(key, 0u, (uint32_t)i);
    } else {
        std::vector<uint32_t> o(2 * n);
        for (int i = 0; i < n; i++) {
            U2 y = threefry(key, (uint32_t)i, (uint32_t)(n + i));
            o[i] = y.a; o[n + i] = y.b;
        }
        for (int j = 0; j < n; j++) out[j] = { o[2 * j], o[2 * j + 1] };
    }
}

static void random_bits32(U2 key, int n, uint32_t* bits) {
    if (kPartitionable) {
        for (int i = 0; i < n; i++) {
            U2 y = threefry(key, 0u, (uint32_t)i);
            bits[i] = y.a ^ y.b;
        }
    } else {
        int h = n / 2;
        for (int i = 0; i < h; i++) {
            U2 y = threefry(key, (uint32_t)i, (uint32_t)(h + i));
            bits[i] = y.a; bits[h + i] = y.b;
        }
    }
}

static void compute_init_indices(int out_idx[kRC]) {
    U2 master{0u, 1234u};
    U2 runkeys[kNR];
    split_keys(master, kNR, runkeys);
    std::vector<int> val(kN), tmp(kN);
    std::vector<uint64_t> kv(kN);
    std::vector<uint32_t> bits(kN);
    for (int r = 0; r < kNR; r++) {
        for (int i = 0; i < kN; i++) val[i] = i;
        U2 cur = runkeys[r];
        for (int round = 0; round < 2; round++) {
            U2 nk[2];
            split_keys(cur, 2, nk);
            cur = nk[0];
            random_bits32(nk[1], kN, bits.data());
            for (int i = 0; i < kN; i++)
                kv[i] = ((uint64_t)bits[i] << 32) | (uint32_t)i;
            std::sort(kv.begin(), kv.end());
            for (int i = 0; i < kN; i++) tmp[i] = val[(uint32_t)(kv[i] & 0xffffffffu)];
            val.swap(tmp);
        }
        for (int c = 0; c < kNC; c++) out_idx[r * kNC + c] = val[c];
    }
}
} // namespace

// ---------------- device scratch ----------------
__device__ float g_cent[kRC * kD];
__device__ float g_cnorm[kRC];
__device__ int   g_labels[kNR * kN];
__device__ int   g_knn[kN * kTK];

struct IdxArr { int v[kRC]; };

// ---------------- packed fp32x2 helpers (sm_103a FFMA2) ----------------
__device__ __forceinline__ uint64_t f2pack(float lo, float hi) {
    uint64_t r; asm("mov.b64 %0,{%1,%2};" : "=l"(r) : "f"(lo), "f"(hi)); return r;
}
__device__ __forceinline__ void f2unpack(uint64_t v, float& lo, float& hi) {
    asm("mov.b64 {%0,%1},%2;" : "=f"(lo), "=f"(hi) : "l"(v));
}
__device__ __forceinline__ uint64_t ffma2(uint64_t a, uint64_t b, uint64_t c) {
    uint64_t d; asm("fma.rn.f32x2 %0,%1,%2,%3;" : "=l"(d) : "l"(a), "l"(b), "l"(c)); return d;
}

// ---------------- kernel 1: sim GEMM (NT, fp32x2 packed, 128x128x16) ----------------
__global__ void __launch_bounds__(256) gemm_sim_kernel(
    const float* __restrict__ A, const float* __restrict__ B, float* __restrict__ C)
{
    __shared__ __align__(16) float As[16][132];
    __shared__ __align__(16) float Bs[16][132];
    const int m0 = blockIdx.y * 128, n0 = blockIdx.x * 128;
    const int tid = threadIdx.x;
    const int tx = tid & 15, ty = tid >> 4;
    const int lr = tid >> 2, lc = (tid & 3) << 2;

    uint64_t accp[4][8];
#pragma unroll
    for (int p = 0; p < 4; p++)
#pragma unroll
        for (int j = 0; j < 8; j++) accp[p][j] = 0ull;

    for (int k0 = 0; k0 < kD; k0 += 16) {
#pragma unroll
        for (int q = 0; q < 2; q++) {
            float4 v = *reinterpret_cast<const float4*>(&A[(size_t)(m0 + lr + q * 64) * kD + k0 + lc]);
            As[lc + 0][lr + q * 64] = v.x; As[lc + 1][lr + q * 64] = v.y;
            As[lc + 2][lr + q * 64] = v.z; As[lc + 3][lr + q * 64] = v.w;
            float4 w = *reinterpret_cast<const float4*>(&B[(size_t)(n0 + lr + q * 64) * kD + k0 + lc]);
            Bs[lc + 0][lr + q * 64] = w.x; Bs[lc + 1][lr + q * 64] = w.y;
            Bs[lc + 2][lr + q * 64] = w.z; Bs[lc + 3][lr + q * 64] = w.w;
        }
        __syncthreads();
#pragma unroll
        for (int k = 0; k < 16; k++) {
            float4 a0 = *reinterpret_cast<const float4*>(&As[k][ty * 4]);
            float4 a1 = *reinterpret_cast<const float4*>(&As[k][64 + ty * 4]);
            float4 b0 = *reinterpret_cast<const float4*>(&Bs[k][tx * 4]);
            float4 b1 = *reinterpret_cast<const float4*>(&Bs[k][64 + tx * 4]);
            uint64_t pa[4];
            pa[0] = reinterpret_cast<const uint64_t*>(&a0)[0];
            pa[1] = reinterpret_cast<const uint64_t*>(&a0)[1];
            pa[2] = reinterpret_cast<const uint64_t*>(&a1)[0];
            pa[3] = reinterpret_cast<const uint64_t*>(&a1)[1];
            float bv[8] = {b0.x, b0.y, b0.z, b0.w, b1.x, b1.y, b1.z, b1.w};
            uint64_t bb[8];
#pragma unroll
            for (int j = 0; j < 8; j++) bb[j] = f2pack(bv[j], bv[j]);
#pragma unroll
            for (int p = 0; p < 4; p++)
#pragma unroll
                for (int j = 0; j < 8; j++)
                    accp[p][j] = ffma2(pa[p], bb[j], accp[p][j]);
        }
        __syncthreads();
    }
#pragma unroll
    for (int p = 0; p < 4; p++) {
        int base = (p < 2) ? (ty * 4 + 2 * p) : (64 + ty * 4 + 2 * (p - 2));
        float lo[8], hi[8];
#pragma unroll
        for (int j = 0; j < 8; j++) f2unpack(accp[p][j], lo[j], hi[j]);
#pragma unroll
        for (int h = 0; h < 2; h++) {
            int row = m0 + base + h;
            float* vals = h ? hi : lo;
#pragma unroll
            for (int jh = 0; jh < 2; jh++) {
                int col0 = n0 + jh * 64 + tx * 4;
                float4 v;
                v.x = vals[jh * 4 + 0]; v.y = vals[jh * 4 + 1];
                v.z = vals[jh * 4 + 2]; v.w = vals[jh * 4 + 3];
                if (row >= col0 && row < col0 + 4) (&v.x)[row - col0] += 10.f;
                *reinterpret_cast<float4*>(&C[(size_t)row * kN + col0]) = v;
            }
        }
    }
}

// ---------------- kernel 2: per-row top-16 ----------------
__device__ __forceinline__ bool beats(float v1, int i1, float v2, int i2) {
    return (v1 > v2) || (v1 == v2 && i1 < i2);
}

__global__ void __launch_bounds__(256) topk_kernel(const float* __restrict__ sim)
{
    __shared__ float sv[256 * 16];
    __shared__ int   si[256 * 16];
    const int row = blockIdx.x, t = threadIdx.x;
    float tv[16]; int ti[16];
#pragma unroll
    for (int k = 0; k < 16; k++) { tv[k] = -3.402823466e38f; ti[k] = 0x7fffffff; }

    const float* rp = sim + (size_t)row * kN;
    for (int j = t; j < kN; j += 256) {
        float v = rp[j];
        if (beats(v, j, tv[15], ti[15])) {
            float cv = v; int ci = j;
#pragma unroll
            for (int k = 0; k < 16; k++) {
                if (beats(cv, ci, tv[k], ti[k])) {
                    float fv = tv[k]; int fi = ti[k];
                    tv[k] = cv; ti[k] = ci; cv = fv; ci = fi;
                }
            }
        }
    }
#pragma unroll
    for (int k = 0; k < 16; k++) { sv[t * 16 + k] = tv[k]; si[t * 16 + k] = ti[k]; }
    __syncthreads();

    for (int s = 128; s >= 1; s >>= 1) {
        if (t < s) {
            float mv[16]; int mi[16];
            int ia = 0, ib = 0;
#pragma unroll
            for (int k = 0; k < 16; k++) {
                float av = sv[t * 16 + ia], bw = sv[(t + s) * 16 + ib];
                int   ai = si[t * 16 + ia], bj = si[(t + s) * 16 + ib];
                bool ta = beats(av, ai, bw, bj);
                mv[k] = ta ? av : bw; mi[k] = ta ? ai : bj;
                if (ta) ia++; else ib++;
            }
#pragma unroll
            for (int k = 0; k < 16; k++) { sv[t * 16 + k] = mv[k]; si[t * 16 + k] = mi[k]; }
        }
        __syncthreads();
    }
    if (t < kTK) g_knn[row * kTK + t] = si[t];
}

// ---------------- kernel 3: gather init centroids ----------------
__global__ void gather_kernel(const float* __restrict__ X, IdxArr ia)
{
    int b = blockIdx.x;
    int src = ia.v[b];
    for (int d = threadIdx.x; d < kD; d += blockDim.x)
        g_cent[(size_t)b * kD + d] = X[(size_t)src * kD + d];
}

// ---------------- kernel 4: centroid norms (initial) ----------------
__global__ void __launch_bounds__(128) cnorm_kernel()
{
    int rc = blockIdx.x;
    float s = 0.f;
    for (int d = threadIdx.x; d < kD; d += 128) {
        float v = g_cent[(size_t)rc * kD + d];
        s = fmaf(v, v, s);
    }
#pragma unroll
    for (int m = 16; m >= 1; m >>= 1) s += __shfl_xor_sync(0xffffffffu, s, m);
    __shared__ float red[4];
    if ((threadIdx.x & 31) == 0) red[threadIdx.x >> 5] = s;
    __syncthreads();
    if (threadIdx.x == 0) g_cnorm[rc] = red[0] + red[1] + red[2] + red[3];
}

// ---------------- kernel 5: fused dist-GEMM + argmin (fp32x2) ----------------
__global__ void __launch_bounds__(256) assign_kernel(const float* __restrict__ X)
{
    __shared__ __align__(16) float As[16][132];
    __shared__ __align__(16) float Bs[16][68];
    __shared__ float cns[kNC];

    const int r = blockIdx.y, m0 = blockIdx.x * 128;
    const float* B = g_cent + (size_t)r * kNC * kD;
    const int tid = threadIdx.x;
    const int tx = tid & 15, ty = tid >> 4;
    const int lr = tid >> 2, lc = (tid & 3) << 2;

    if (tid < kNC) cns[tid] = g_cnorm[r * kNC + tid];

    uint64_t accp[4][4];
#pragma unroll
    for (int p = 0; p < 4; p++)
#pragma unroll
        for (int j = 0; j < 4; j++) accp[p][j] = 0ull;

    for (int k0 = 0; k0 < kD; k0 += 16) {
#pragma unroll
        for (int q = 0; q < 2; q++) {
            float4 v = *reinterpret_cast<const float4*>(&X[(size_t)(m0 + lr + q * 64) * kD + k0 + lc]);
            As[lc + 0][lr + q * 64] = v.x; As[lc + 1][lr + q * 64] = v.y;
            As[lc + 2][lr + q * 64] = v.z; As[lc + 3][lr + q * 64] = v.w;
        }
        float4 w = *reinterpret_cast<const float4*>(&B[(size_t)lr * kD + k0 + lc]);
        Bs[lc + 0][lr] = w.x; Bs[lc + 1][lr] = w.y;
        Bs[lc + 2][lr] = w.z; Bs[lc + 3][lr] = w.w;
        __syncthreads();
#pragma unroll
        for (int k = 0; k < 16; k++) {
            float4 a0 = *reinterpret_cast<const float4*>(&As[k][ty * 4]);
            float4 a1 = *reinterpret_cast<const float4*>(&As[k][64 + ty * 4]);
            float4 b  = *reinterpret_cast<const float4*>(&Bs[k][tx * 4]);
            uint64_t pa[4];
            pa[0] = reinterpret_cast<const uint64_t*>(&a0)[0];
            pa[1] = reinterpret_cast<const uint64_t*>(&a0)[1];
            pa[2] = reinterpret_cast<const uint64_t*>(&a1)[0];
            pa[3] = reinterpret_cast<const uint64_t*>(&a1)[1];
            float bv[4] = {b.x, b.y, b.z, b.w};
            uint64_t bb[4];
#pragma unroll
            for (int j = 0; j < 4; j++) bb[j] = f2pack(bv[j], bv[j]);
#pragma unroll
            for (int p = 0; p < 4; p++)
#pragma unroll
                for (int j = 0; j < 4; j++)
                    accp[p][j] = ffma2(pa[p], bb[j], accp[p][j]);
        }
        __syncthreads();
    }
#pragma unroll
    for (int p = 0; p < 4; p++) {
        int base = (p < 2) ? (ty * 4 + 2 * p) : (64 + ty * 4 + 2 * (p - 2));
        float lo[4], hi[4];
#pragma unroll
        for (int j = 0; j < 4; j++) f2unpack(accp[p][j], lo[j], hi[j]);
#pragma unroll
        for (int h = 0; h < 2; h++) {
            float* vals = h ? hi : lo;
            float bvm = cns[tx * 4] - 2.f * vals[0];
            int   bi  = tx * 4;
#pragma unroll
            for (int j = 1; j < 4; j++) {
                float v = cns[tx * 4 + j] - 2.f * vals[j];
                if (v < bvm) { bvm = v; bi = tx * 4 + j; }
            }
#pragma unroll
            for (int m = 1; m < 16; m <<= 1) {
                float ov = __shfl_xor_sync(0xffffffffu, bvm, m);
                int   oi = __shfl_xor_sync(0xffffffffu, bi, m);
                if (ov < bvm || (ov == bvm && oi < bi)) { bvm = ov; bi = oi; }
            }
            if (tx == 0) g_labels[r * kN + m0 + base + h] = bi;
        }
    }
}

// ---------------- kernel 6: deterministic centroid update + norm ----------------
__global__ void __launch_bounds__(512) update_kernel(const float* __restrict__ X)
{
    __shared__ int list[kN];
    __shared__ int wsum[16];
    __shared__ int total_s;
    __shared__ float fred[16];

    const int c = blockIdx.x, r = blockIdx.y;
    const int t = threadIdx.x;
    const unsigned lane = t & 31;
    const int* lab = g_labels + r * kN;

    int mybuf[16];
    int cnt = 0;
    const int p0 = t * 16;
#pragma unroll
    for (int q = 0; q < 16; q++) {
        int p = p0 + q;
        if (lab[p] == c) mybuf[cnt++] = p;
    }
    int incl = cnt;
#pragma unroll
    for (int off = 1; off < 32; off <<= 1) {
        int y = __shfl_up_sync(0xffffffffu, incl, off);
        if (lane >= off) incl += y;
    }
    if (lane == 31) wsum[t >> 5] = incl;
    __syncthreads();
    if (t < 16) {
        int v = wsum[t], s = v;
#pragma unroll
        for (int off = 1; off < 16; off <<= 1) {
            int y = __shfl_up_sync(0x0000ffffu, s, off);
            if ((int)t >= off) s += y;
        }
        wsum[t] = s - v;
    }
    __syncthreads();
    int offset = wsum[t >> 5] + incl - cnt;
    for (int q = 0; q < cnt; q++) list[offset + q] = mybuf[q];
    if (t == 511) total_s = offset + cnt;
    __syncthreads();

    const int total = total_s;
    float sum = 0.f;
    int i = 0;
    for (; i + 4 <= total; i += 4) {                 // MLP=4, exact same add order
        int q0 = list[i], q1 = list[i + 1], q2 = list[i + 2], q3 = list[i + 3];
        float v0 = X[(size_t)q0 * kD + t];
        float v1 = X[(size_t)q1 * kD + t];
        float v2 = X[(size_t)q2 * kD + t];
        float v3 = X[(size_t)q3 * kD + t];
        sum += v0; sum += v1; sum += v2; sum += v3;
    }
    for (; i < total; i++) sum += X[(size_t)list[i] * kD + t];

    const int rc = r * kNC + c;
    float oldc = g_cent[(size_t)rc * kD + t];
    float newc = (total > 0) ? (sum / (float)total) : oldc;
    g_cent[(size_t)rc * kD + t] = newc;

    float sq = newc * newc;
#pragma unroll
    for (int m = 16; m >= 1; m >>= 1) sq += __shfl_xor_sync(0xffffffffu, sq, m);
    if (lane == 0) fred[t >> 5] = sq;
    __syncthreads();
    if (t == 0) {
        float s = 0.f;
        for (int w = 0; w < 16; w++) s += fred[w];
        g_cnorm[rc] = s;
    }
}

// ---------------- kernel 7: scatter final output ----------------
__global__ void __launch_bounds__(256) scatter_kernel(
    const float* __restrict__ adj, float* __restrict__ out)
{
    int e = blockIdx.x * blockDim.x + threadIdx.x;
    int i = e >> 4;
    int j = g_knn[e];
    float v = adj[(size_t)i * kN + j];
    bool m = false;
#pragma unroll
    for (int r = 0; r < kNR; r++)
        m |= (g_labels[r * kN + i] == g_labels[r * kN + j]);
    out[(size_t)i * kN + j] = v + (m ? 1.f : 0.f);
}

// ---------------- launcher: two-stream overlap ----------------
extern "C" void kernel_launch(void* const* d_in, const int* in_sizes, int n_in,
                              void* d_out, int out_size)
{
    (void)in_sizes; (void)n_in; (void)out_size;
    const float* adj     = (const float*)d_in[0];
    const float* student = (const float*)d_in[1];
    const float* teacher = (const float*)d_in[2];
    float* out = (float*)d_out;

    static cudaStream_t s2 = nullptr;
    static cudaEvent_t ev_fork = nullptr, ev_join = nullptr;
    if (!s2) {
        cudaStreamCreateWithFlags(&s2, cudaStreamNonBlocking);
        cudaEventCreateWithFlags(&ev_fork, cudaEventDisableTiming);
        cudaEventCreateWithFlags(&ev_join, cudaEventDisableTiming);
    }

    IdxArr ia;
    compute_init_indices(ia.v);

    // fork: kmeans chain (teacher only) on s2
    cudaEventRecord(ev_fork, 0);
    cudaStreamWaitEvent(s2, ev_fork, 0);

    gather_kernel<<<kRC, 128, 0, s2>>>(teacher, ia);
    cnorm_kernel<<<kRC, 128, 0, s2>>>();
    dim3 ga(kN / 128, kNR), gu(kNC, kNR);
    for (int it = 0; it < kIters; it++) {
        assign_kernel<<<ga, 256, 0, s2>>>(teacher);
        update_kernel<<<gu, 512, 0, s2>>>(teacher);
    }
    assign_kernel<<<ga, 256, 0, s2>>>(teacher);
    cudaEventRecord(ev_join, s2);

    // main stream: sim GEMM -> topk -> zero out
    dim3 g1(kN / 128, kN / 128);
    gemm_sim_kernel<<<g1, 256>>>(student, teacher, out);
    topk_kernel<<<kN, 256>>>(out);
    cudaMemsetAsync(d_out, 0, (size_t)kN * kN * sizeof(float), 0);

    // join + scatter
    cudaStreamWaitEvent(0, ev_join, 0);
    scatter_kernel<<<kN * kTK / 256, 256>>>(adj, out);
}

// round 5
// speedup vs baseline: 1.1046x; 1.0135x over previous
#include <cuda_runtime.h>
#include <cstdint>
#include <cstring>
#include <vector>
#include <algorithm>

namespace {
constexpr int kN = 8192, kD = 512, kNC = 64, kNR = 5, kRC = kNC * kNR;
constexpr int kTK = 16, kIters = 20;
constexpr int kCH = 16, kCHP = kN / kCH;   // 16 chunks x 512 points

// ---------------- host-side JAX threefry2x32 ----------------
struct U2 { uint32_t a, b; };
static inline uint32_t rotl32(uint32_t v, int r) { return (v << r) | (v >> (32 - r)); }

static U2 threefry(U2 key, uint32_t x0, uint32_t x1) {
    uint32_t ks0 = key.a, ks1 = key.b, ks2 = key.a ^ key.b ^ 0x1BD11BDAu;
    const int ra[4] = {13, 15, 26, 6}, rb[4] = {17, 29, 16, 24};
    x0 += ks0; x1 += ks1;
    for (int i = 0; i < 4; i++) { x0 += x1; x1 = rotl32(x1, ra[i]); x1 ^= x0; }
    x0 += ks1; x1 += ks2 + 1u;
    for (int i = 0; i < 4; i++) { x0 += x1; x1 = rotl32(x1, rb[i]); x1 ^= x0; }
    x0 += ks2; x1 += ks0 + 2u;
    for (int i = 0; i < 4; i++) { x0 += x1; x1 = rotl32(x1, ra[i]); x1 ^= x0; }
    x0 += ks0; x1 += ks1 + 3u;
    for (int i = 0; i < 4; i++) { x0 += x1; x1 = rotl32(x1, rb[i]); x1 ^= x0; }
    x0 += ks1; x1 += ks2 + 4u;
    for (int i = 0; i < 4; i++) { x0 += x1; x1 = rotl32(x1, ra[i]); x1 ^= x0; }
    x0 += ks2; x1 += ks0 + 5u;
    return {x0, x1};
}

constexpr bool kPartitionable = true;

static void split_keys(U2 key, int n, U2* out) {
    if (kPartitionable) {
        for (int i = 0; i < n; i++) out[i] = threefry(key, 0u, (uint32_t)i);
    } else {
        std::vector<uint32_t> o(2 * n);
        for (int i = 0; i < n; i++) {
            U2 y = threefry(key, (uint32_t)i, (uint32_t)(n + i));
            o[i] = y.a; o[n + i] = y.b;
        }
        for (int j = 0; j < n; j++) out[j] = { o[2 * j], o[2 * j + 1] };
    }
}

static void random_bits32(U2 key, int n, uint32_t* bits) {
    if (kPartitionable) {
        for (int i = 0; i < n; i++) {
            U2 y = threefry(key, 0u, (uint32_t)i);
            bits[i] = y.a ^ y.b;
        }
    } else {
        int h = n / 2;
        for (int i = 0; i < h; i++) {
            U2 y = threefry(key, (uint32_t)i, (uint32_t)(h + i));
            bits[i] = y.a; bits[h + i] = y.b;
        }
    }
}

static void compute_init_indices(int out_idx[kRC]) {
    U2 master{0u, 1234u};
    U2 runkeys[kNR];
    split_keys(master, kNR, runkeys);
    std::vector<int> val(kN), tmp(kN);
    std::vector<uint64_t> kv(kN);
    std::vector<uint32_t> bits(kN);
    for (int r = 0; r < kNR; r++) {
        for (int i = 0; i < kN; i++) val[i] = i;
        U2 cur = runkeys[r];
        for (int round = 0; round < 2; round++) {
            U2 nk[2];
            split_keys(cur, 2, nk);
            cur = nk[0];
            random_bits32(nk[1], kN, bits.data());
            for (int i = 0; i < kN; i++)
                kv[i] = ((uint64_t)bits[i] << 32) | (uint32_t)i;
            std::sort(kv.begin(), kv.end());
            for (int i = 0; i < kN; i++) tmp[i] = val[(uint32_t)(kv[i] & 0xffffffffu)];
            val.swap(tmp);
        }
        for (int c = 0; c < kNC; c++) out_idx[r * kNC + c] = val[c];
    }
}
} // namespace

// ---------------- device scratch ----------------
__device__ float g_cent[kRC * kD];
__device__ float g_cnorm[kRC];
__device__ int   g_labels[kNR * kN];
__device__ int   g_knn[kN * kTK];
__device__ float g_part[(size_t)kNR * kCH * kNC * kD];   // 10.5 MB
__device__ int   g_pcnt[kNR * kCH * kNC];

struct IdxArr { int v[kRC]; };

// ---------------- packed fp32x2 helpers (sm_103a FFMA2) ----------------
__device__ __forceinline__ uint64_t f2pack(float lo, float hi) {
    uint64_t r; asm("mov.b64 %0,{%1,%2};" : "=l"(r) : "f"(lo), "f"(hi)); return r;
}
__device__ __forceinline__ void f2unpack(uint64_t v, float& lo, float& hi) {
    asm("mov.b64 {%0,%1},%2;" : "=f"(lo), "=f"(hi) : "l"(v));
}
__device__ __forceinline__ uint64_t ffma2(uint64_t a, uint64_t b, uint64_t c) {
    uint64_t d; asm("fma.rn.f32x2 %0,%1,%2,%3;" : "=l"(d) : "l"(a), "l"(b), "l"(c)); return d;
}

// ---------------- kernel 1: sim GEMM (NT, fp32x2 packed, 128x128x16) ----------------
__global__ void __launch_bounds__(256) gemm_sim_kernel(
    const float* __restrict__ A, const float* __restrict__ B, float* __restrict__ C)
{
    __shared__ __align__(16) float As[16][132];
    __shared__ __align__(16) float Bs[16][132];
    const int m0 = blockIdx.y * 128, n0 = blockIdx.x * 128;
    const int tid = threadIdx.x;
    const int tx = tid & 15, ty = tid >> 4;
    const int lr = tid >> 2, lc = (tid & 3) << 2;

    uint64_t accp[4][8];
#pragma unroll
    for (int p = 0; p < 4; p++)
#pragma unroll
        for (int j = 0; j < 8; j++) accp[p][j] = 0ull;

    for (int k0 = 0; k0 < kD; k0 += 16) {
#pragma unroll
        for (int q = 0; q < 2; q++) {
            float4 v = *reinterpret_cast<const float4*>(&A[(size_t)(m0 + lr + q * 64) * kD + k0 + lc]);
            As[lc + 0][lr + q * 64] = v.x; As[lc + 1][lr + q * 64] = v.y;
            As[lc + 2][lr + q * 64] = v.z; As[lc + 3][lr + q * 64] = v.w;
            float4 w = *reinterpret_cast<const float4*>(&B[(size_t)(n0 + lr + q * 64) * kD + k0 + lc]);
            Bs[lc + 0][lr + q * 64] = w.x; Bs[lc + 1][lr + q * 64] = w.y;
            Bs[lc + 2][lr + q * 64] = w.z; Bs[lc + 3][lr + q * 64] = w.w;
        }
        __syncthreads();
#pragma unroll
        for (int k = 0; k < 16; k++) {
            float4 a0 = *reinterpret_cast<const float4*>(&As[k][ty * 4]);
            float4 a1 = *reinterpret_cast<const float4*>(&As[k][64 + ty * 4]);
            float4 b0 = *reinterpret_cast<const float4*>(&Bs[k][tx * 4]);
            float4 b1 = *reinterpret_cast<const float4*>(&Bs[k][64 + tx * 4]);
            uint64_t pa[4];
            pa[0] = reinterpret_cast<const uint64_t*>(&a0)[0];
            pa[1] = reinterpret_cast<const uint64_t*>(&a0)[1];
            pa[2] = reinterpret_cast<const uint64_t*>(&a1)[0];
            pa[3] = reinterpret_cast<const uint64_t*>(&a1)[1];
            float bv[8] = {b0.x, b0.y, b0.z, b0.w, b1.x, b1.y, b1.z, b1.w};
            uint64_t bb[8];
#pragma unroll
            for (int j = 0; j < 8; j++) bb[j] = f2pack(bv[j], bv[j]);
#pragma unroll
            for (int p = 0; p < 4; p++)
#pragma unroll
                for (int j = 0; j < 8; j++)
                    accp[p][j] = ffma2(pa[p], bb[j], accp[p][j]);
        }
        __syncthreads();
    }
#pragma unroll
    for (int p = 0; p < 4; p++) {
        int base = (p < 2) ? (ty * 4 + 2 * p) : (64 + ty * 4 + 2 * (p - 2));
        float lo[8], hi[8];
#pragma unroll
        for (int j = 0; j < 8; j++) f2unpack(accp[p][j], lo[j], hi[j]);
#pragma unroll
        for (int h = 0; h < 2; h++) {
            int row = m0 + base + h;
            float* vals = h ? hi : lo;
#pragma unroll
            for (int jh = 0; jh < 2; jh++) {
                int col0 = n0 + jh * 64 + tx * 4;
                float4 v;
                v.x = vals[jh * 4 + 0]; v.y = vals[jh * 4 + 1];
                v.z = vals[jh * 4 + 2]; v.w = vals[jh * 4 + 3];
                if (row >= col0 && row < col0 + 4) (&v.x)[row - col0] += 10.f;
                *reinterpret_cast<float4*>(&C[(size_t)row * kN + col0]) = v;
            }
        }
    }
}

// ---------------- kernel 2: per-row top-16 ----------------
__device__ __forceinline__ bool beats(float v1, int i1, float v2, int i2) {
    return (v1 > v2) || (v1 == v2 && i1 < i2);
}

__global__ void __launch_bounds__(256) topk_kernel(const float* __restrict__ sim)
{
    __shared__ float sv[256 * 16];
    __shared__ int   si[256 * 16];
    const int row = blockIdx.x, t = threadIdx.x;
    float tv[16]; int ti[16];
#pragma unroll
    for (int k = 0; k < 16; k++) { tv[k] = -3.402823466e38f; ti[k] = 0x7fffffff; }

    const float* rp = sim + (size_t)row * kN;
    for (int j = t; j < kN; j += 256) {
        float v = rp[j];
        if (beats(v, j, tv[15], ti[15])) {
            float cv = v; int ci = j;
#pragma unroll
            for (int k = 0; k < 16; k++) {
                if (beats(cv, ci, tv[k], ti[k])) {
                    float fv = tv[k]; int fi = ti[k];
                    tv[k] = cv; ti[k] = ci; cv = fv; ci = fi;
                }
            }
        }
    }
#pragma unroll
    for (int k = 0; k < 16; k++) { sv[t * 16 + k] = tv[k]; si[t * 16 + k] = ti[k]; }
    __syncthreads();

    for (int s = 128; s >= 1; s >>= 1) {
        if (t < s) {
            float mv[16]; int mi[16];
            int ia = 0, ib = 0;
#pragma unroll
            for (int k = 0; k < 16; k++) {
                float av = sv[t * 16 + ia], bw = sv[(t + s) * 16 + ib];
                int   ai = si[t * 16 + ia], bj = si[(t + s) * 16 + ib];
                bool ta = beats(av, ai, bw, bj);
                mv[k] = ta ? av : bw; mi[k] = ta ? ai : bj;
                if (ta) ia++; else ib++;
            }
#pragma unroll
            for (int k = 0; k < 16; k++) { sv[t * 16 + k] = mv[k]; si[t * 16 + k] = mi[k]; }
        }
        __syncthreads();
    }
    if (t < kTK) g_knn[row * kTK + t] = si[t];
}

// ---------------- kernel 3: gather init centroids ----------------
__global__ void gather_kernel(const float* __restrict__ X, IdxArr ia)
{
    int b = blockIdx.x;
    int src = ia.v[b];
    for (int d = threadIdx.x; d < kD; d += blockDim.x)
        g_cent[(size_t)b * kD + d] = X[(size_t)src * kD + d];
}

// ---------------- kernel 4: centroid norms (initial) ----------------
__global__ void __launch_bounds__(128) cnorm_kernel()
{
    int rc = blockIdx.x;
    float s = 0.f;
    for (int d = threadIdx.x; d < kD; d += 128) {
        float v = g_cent[(size_t)rc * kD + d];
        s = fmaf(v, v, s);
    }
#pragma unroll
    for (int m = 16; m >= 1; m >>= 1) s += __shfl_xor_sync(0xffffffffu, s, m);
    __shared__ float red[4];
    if ((threadIdx.x & 31) == 0) red[threadIdx.x >> 5] = s;
    __syncthreads();
    if (threadIdx.x == 0) g_cnorm[rc] = red[0] + red[1] + red[2] + red[3];
}

// ---------------- kernel 5: fused dist-GEMM + argmin (fp32x2) ----------------
__global__ void __launch_bounds__(256) assign_kernel(const float* __restrict__ X)
{
    __shared__ __align__(16) float As[16][132];
    __shared__ __align__(16) float Bs[16][68];
    __shared__ float cns[kNC];

    const int r = blockIdx.y, m0 = blockIdx.x * 128;
    const float* B = g_cent + (size_t)r * kNC * kD;
    const int tid = threadIdx.x;
    const int tx = tid & 15, ty = tid >> 4;
    const int lr = tid >> 2, lc = (tid & 3) << 2;

    if (tid < kNC) cns[tid] = g_cnorm[r * kNC + tid];

    uint64_t accp[4][4];
#pragma unroll
    for (int p = 0; p < 4; p++)
#pragma unroll
        for (int j = 0; j < 4; j++) accp[p][j] = 0ull;

    for (int k0 = 0; k0 < kD; k0 += 16) {
#pragma unroll
        for (int q = 0; q < 2; q++) {
            float4 v = *reinterpret_cast<const float4*>(&X[(size_t)(m0 + lr + q * 64) * kD + k0 + lc]);
            As[lc + 0][lr + q * 64] = v.x; As[lc + 1][lr + q * 64] = v.y;
            As[lc + 2][lr + q * 64] = v.z; As[lc + 3][lr + q * 64] = v.w;
        }
        float4 w = *reinterpret_cast<const float4*>(&B[(size_t)lr * kD + k0 + lc]);
        Bs[lc + 0][lr] = w.x; Bs[lc + 1][lr] = w.y;
        Bs[lc + 2][lr] = w.z; Bs[lc + 3][lr] = w.w;
        __syncthreads();
#pragma unroll
        for (int k = 0; k < 16; k++) {
            float4 a0 = *reinterpret_cast<const float4*>(&As[k][ty * 4]);
            float4 a1 = *reinterpret_cast<const float4*>(&As[k][64 + ty * 4]);
            float4 b  = *reinterpret_cast<const float4*>(&Bs[k][tx * 4]);
            uint64_t pa[4];
            pa[0] = reinterpret_cast<const uint64_t*>(&a0)[0];
            pa[1] = reinterpret_cast<const uint64_t*>(&a0)[1];
            pa[2] = reinterpret_cast<const uint64_t*>(&a1)[0];
            pa[3] = reinterpret_cast<const uint64_t*>(&a1)[1];
            float bv[4] = {b.x, b.y, b.z, b.w};
            uint64_t bb[4];
#pragma unroll
            for (int j = 0; j < 4; j++) bb[j] = f2pack(bv[j], bv[j]);
#pragma unroll
            for (int p = 0; p < 4; p++)
#pragma unroll
                for (int j = 0; j < 4; j++)
                    accp[p][j] = ffma2(pa[p], bb[j], accp[p][j]);
        }
        __syncthreads();
    }
#pragma unroll
    for (int p = 0; p < 4; p++) {
        int base = (p < 2) ? (ty * 4 + 2 * p) : (64 + ty * 4 + 2 * (p - 2));
        float lo[4], hi[4];
#pragma unroll
        for (int j = 0; j < 4; j++) f2unpack(accp[p][j], lo[j], hi[j]);
#pragma unroll
        for (int h = 0; h < 2; h++) {
            float* vals = h ? hi : lo;
            float bvm = cns[tx * 4] - 2.f * vals[0];
            int   bi  = tx * 4;
#pragma unroll
            for (int j = 1; j < 4; j++) {
                float v = cns[tx * 4 + j] - 2.f * vals[j];
                if (v < bvm) { bvm = v; bi = tx * 4 + j; }
            }
#pragma unroll
            for (int m = 1; m < 16; m <<= 1) {
                float ov = __shfl_xor_sync(0xffffffffu, bvm, m);
                int   oi = __shfl_xor_sync(0xffffffffu, bi, m);
                if (ov < bvm || (ov == bvm && oi < bi)) { bvm = ov; bi = oi; }
            }
            if (tx == 0) g_labels[r * kN + m0 + base + h] = bi;
        }
    }
}

// ---------------- kernel 6a: point-centric partial sums (streaming) ----------------
// grid (kCH, kNR), 512 threads, dynamic smem = 64*512 floats + 512 + 64 ints
__global__ void __launch_bounds__(512) partial_kernel(const float* __restrict__ X)
{
    extern __shared__ float sm[];
    float* ssum = sm;                          // [kNC][kD]
    int*   slab = (int*)(sm + kNC * kD);       // [kCHP]
    int*   scnt = (int*)(sm + kNC * kD) + kCHP;// [kNC]

    const int ch = blockIdx.x, r = blockIdx.y;
    const int t = threadIdx.x;                 // dim (kD == 512 == blockDim)
    const int p0 = ch * kCHP;
    const int* lab = g_labels + r * kN;

#pragma unroll
    for (int c = 0; c < kNC; c++) ssum[c * kD + t] = 0.f;
    if (t < kNC) scnt[t] = 0;
    slab[t] = lab[p0 + t];
    __syncthreads();
    atomicAdd(&scnt[slab[t]], 1);              // exact integer counts
    __syncthreads();

    // ascending point order; 4-way MLP on the X loads, adds stay sequential
    for (int i = 0; i < kCHP; i += 4) {
        float x0 = X[(size_t)(p0 + i + 0) * kD + t];
        float x1 = X[(size_t)(p0 + i + 1) * kD + t];
        float x2 = X[(size_t)(p0 + i + 2) * kD + t];
        float x3 = X[(size_t)(p0 + i + 3) * kD + t];
        int c0 = slab[i + 0], c1 = slab[i + 1], c2 = slab[i + 2], c3 = slab[i + 3];
        ssum[c0 * kD + t] += x0;
        ssum[c1 * kD + t] += x1;
        ssum[c2 * kD + t] += x2;
        ssum[c3 * kD + t] += x3;
    }
    __syncthreads();

    const size_t base = (size_t)(r * kCH + ch) * kNC;
#pragma unroll
    for (int c = 0; c < kNC; c++)
        g_part[(base + c) * kD + t] = ssum[c * kD + t];
    if (t < kNC) g_pcnt[base + t] = scnt[t];
}

// ---------------- kernel 6b: combine partials -> centroid + norm ----------------
__global__ void __launch_bounds__(512) combine_kernel()
{
    __shared__ float fred[16];
    const int c = blockIdx.x, r = blockIdx.y;
    const int t = threadIdx.x;                 // dim
    const unsigned lane = t & 31;

    int cnt = 0;
    float sum = 0.f;
#pragma unroll
    for (int ch = 0; ch < kCH; ch++) {         // fixed ascending chunk order
        size_t base = (size_t)(r * kCH + ch) * kNC + c;
        cnt += g_pcnt[base];
        sum += g_part[base * kD + t];
    }
    const int rc = r * kNC + c;
    float oldc = g_cent[(size_t)rc * kD + t];
    float newc = (cnt > 0) ? (sum / (float)cnt) : oldc;
    g_cent[(size_t)rc * kD + t] = newc;

    float sq = newc * newc;
#pragma unroll
    for (int m = 16; m >= 1; m >>= 1) sq += __shfl_xor_sync(0xffffffffu, sq, m);
    if (lane == 0) fred[t >> 5] = sq;
    __syncthreads();
    if (t == 0) {
        float s = 0.f;
        for (int w = 0; w < 16; w++) s += fred[w];
        g_cnorm[rc] = s;
    }
}

// ---------------- kernel 7: scatter final output ----------------
__global__ void __launch_bounds__(256) scatter_kernel(
    const float* __restrict__ adj, float* __restrict__ out)
{
    int e = blockIdx.x * blockDim.x + threadIdx.x;
    int i = e >> 4;
    int j = g_knn[e];
    float v = adj[(size_t)i * kN + j];
    bool m = false;
#pragma unroll
    for (int r = 0; r < kNR; r++)
        m |= (g_labels[r * kN + i] == g_labels[r * kN + j]);
    out[(size_t)i * kN + j] = v + (m ? 1.f : 0.f);
}

// ---------------- launcher: two-stream overlap ----------------
extern "C" void kernel_launch(void* const* d_in, const int* in_sizes, int n_in,
                              void* d_out, int out_size)
{
    (void)in_sizes; (void)n_in; (void)out_size;
    const float* adj     = (const float*)d_in[0];
    const float* student = (const float*)d_in[1];
    const float* teacher = (const float*)d_in[2];
    float* out = (float*)d_out;

    constexpr size_t kPartSmem = (size_t)kNC * kD * 4 + kCHP * 4 + kNC * 4; // ~132.3 KB
    static cudaStream_t s2 = nullptr;
    static cudaEvent_t ev_fork = nullptr, ev_join = nullptr;
    if (!s2) {
        cudaStreamCreateWithFlags(&s2, cudaStreamNonBlocking);
        cudaEventCreateWithFlags(&ev_fork, cudaEventDisableTiming);
        cudaEventCreateWithFlags(&ev_join, cudaEventDisableTiming);
        cudaFuncSetAttribute(partial_kernel,
                             cudaFuncAttributeMaxDynamicSharedMemorySize, (int)kPartSmem);
    }

    IdxArr ia;
    compute_init_indices(ia.v);

    // fork: kmeans chain (teacher only) on s2
    cudaEventRecord(ev_fork, 0);
    cudaStreamWaitEvent(s2, ev_fork, 0);

    gather_kernel<<<kRC, 128, 0, s2>>>(teacher, ia);
    cnorm_kernel<<<kRC, 128, 0, s2>>>();
    dim3 ga(kN / 128, kNR), gp(kCH, kNR), gc(kNC, kNR);
    for (int it = 0; it < kIters; it++) {
        assign_kernel<<<ga, 256, 0, s2>>>(teacher);
        partial_kernel<<<gp, 512, kPartSmem, s2>>>(teacher);
        combine_kernel<<<gc, 512, 0, s2>>>();
    }
    assign_kernel<<<ga, 256, 0, s2>>>(teacher);
    cudaEventRecord(ev_join, s2);

    // main stream: sim GEMM -> topk -> zero out
    dim3 g1(kN / 128, kN / 128);
    gemm_sim_kernel<<<g1, 256>>>(student, teacher, out);
    topk_kernel<<<kN, 256>>>(out);
    cudaMemsetAsync(d_out, 0, (size_t)kN * kN * sizeof(float), 0);

    // join + scatter
    cudaStreamWaitEvent(0, ev_join, 0);
    scatter_kernel<<<kN * kTK / 256, 256>>>(adj, out);
}

// round 6
// speedup vs baseline: 1.1622x; 1.0521x over previous
#include <cuda_runtime.h>
#include <cstdint>
#include <cstring>
#include <vector>
#include <algorithm>

namespace {
constexpr int kN = 8192, kD = 512, kNC = 64, kNR = 5, kRC = kNC * kNR;
constexpr int kTK = 16, kIters = 20;
constexpr int kCH = 32, kCHP = kN / kCH;   // 32 chunks x 256 points

// ---------------- host-side JAX threefry2x32 ----------------
struct U2 { uint32_t a, b; };
static inline uint32_t rotl32(uint32_t v, int r) { return (v << r) | (v >> (32 - r)); }

static U2 threefry(U2 key, uint32_t x0, uint32_t x1) {
    uint32_t ks0 = key.a, ks1 = key.b, ks2 = key.a ^ key.b ^ 0x1BD11BDAu;
    const int ra[4] = {13, 15, 26, 6}, rb[4] = {17, 29, 16, 24};
    x0 += ks0; x1 += ks1;
    for (int i = 0; i < 4; i++) { x0 += x1; x1 = rotl32(x1, ra[i]); x1 ^= x0; }
    x0 += ks1; x1 += ks2 + 1u;
    for (int i = 0; i < 4; i++) { x0 += x1; x1 = rotl32(x1, rb[i]); x1 ^= x0; }
    x0 += ks2; x1 += ks0 + 2u;
    for (int i = 0; i < 4; i++) { x0 += x1; x1 = rotl32(x1, ra[i]); x1 ^= x0; }
    x0 += ks0; x1 += ks1 + 3u;
    for (int i = 0; i < 4; i++) { x0 += x1; x1 = rotl32(x1, rb[i]); x1 ^= x0; }
    x0 += ks1; x1 += ks2 + 4u;
    for (int i = 0; i < 4; i++) { x0 += x1; x1 = rotl32(x1, ra[i]); x1 ^= x0; }
    x0 += ks2; x1 += ks0 + 5u;
    return {x0, x1};
}

constexpr bool kPartitionable = true;

static void split_keys(U2 key, int n, U2* out) {
    if (kPartitionable) {
        for (int i = 0; i < n; i++) out[i] = threefry(key, 0u, (uint32_t)i);
    } else {
        std::vector<uint32_t> o(2 * n);
        for (int i = 0; i < n; i++) {
            U2 y = threefry(key, (uint32_t)i, (uint32_t)(n + i));
            o[i] = y.a; o[n + i] = y.b;
        }
        for (int j = 0; j < n; j++) out[j] = { o[2 * j], o[2 * j + 1] };
    }
}

static void random_bits32(U2 key, int n, uint32_t* bits) {
    if (kPartitionable) {
        for (int i = 0; i < n; i++) {
            U2 y = threefry(key, 0u, (uint32_t)i);
            bits[i] = y.a ^ y.b;
        }
    } else {
        int h = n / 2;
        for (int i = 0; i < h; i++) {
            U2 y = threefry(key, (uint32_t)i, (uint32_t)(h + i));
            bits[i] = y.a; bits[h + i] = y.b;
        }
    }
}

static void compute_init_indices(int out_idx[kRC]) {
    U2 master{0u, 1234u};
    U2 runkeys[kNR];
    split_keys(master, kNR, runkeys);
    std::vector<int> val(kN), tmp(kN);
    std::vector<uint64_t> kv(kN);
    std::vector<uint32_t> bits(kN);
    for (int r = 0; r < kNR; r++) {
        for (int i = 0; i < kN; i++) val[i] = i;
        U2 cur = runkeys[r];
        for (int round = 0; round < 2; round++) {
            U2 nk[2];
            split_keys(cur, 2, nk);
            cur = nk[0];
            random_bits32(nk[1], kN, bits.data());
            for (int i = 0; i < kN; i++)
                kv[i] = ((uint64_t)bits[i] << 32) | (uint32_t)i;
            std::sort(kv.begin(), kv.end());
            for (int i = 0; i < kN; i++) tmp[i] = val[(uint32_t)(kv[i] & 0xffffffffu)];
            val.swap(tmp);
        }
        for (int c = 0; c < kNC; c++) out_idx[r * kNC + c] = val[c];
    }
}
} // namespace

// ---------------- device scratch ----------------
__device__ float g_cent[kRC * kD];
__device__ float g_cnorm[kRC];
__device__ int   g_labels[kNR * kN];
__device__ int   g_knn[kN * kTK];
__device__ float g_part[(size_t)kNR * kCH * kNC * kD];   // 21 MB
__device__ int   g_pcnt[kNR * kCH * kNC];

struct IdxArr { int v[kRC]; };

// ---------------- packed fp32x2 helpers (sm_103a FFMA2) ----------------
__device__ __forceinline__ uint64_t f2pack(float lo, float hi) {
    uint64_t r; asm("mov.b64 %0,{%1,%2};" : "=l"(r) : "f"(lo), "f"(hi)); return r;
}
__device__ __forceinline__ void f2unpack(uint64_t v, float& lo, float& hi) {
    asm("mov.b64 {%0,%1},%2;" : "=f"(lo), "=f"(hi) : "l"(v));
}
__device__ __forceinline__ uint64_t ffma2(uint64_t a, uint64_t b, uint64_t c) {
    uint64_t d; asm("fma.rn.f32x2 %0,%1,%2,%3;" : "=l"(d) : "l"(a), "l"(b), "l"(c)); return d;
}

// ---------------- kernel 1: sim GEMM (prefetch double-buffered) ----------------
__global__ void __launch_bounds__(256) gemm_sim_kernel(
    const float* __restrict__ A, const float* __restrict__ B, float* __restrict__ C)
{
    __shared__ __align__(16) float As[16][132];
    __shared__ __align__(16) float Bs[16][132];
    const int m0 = blockIdx.y * 128, n0 = blockIdx.x * 128;
    const int tid = threadIdx.x;
    const int tx = tid & 15, ty = tid >> 4;
    const int lr = tid >> 2, lc = (tid & 3) << 2;

    uint64_t accp[4][8];
#pragma unroll
    for (int p = 0; p < 4; p++)
#pragma unroll
        for (int j = 0; j < 8; j++) accp[p][j] = 0ull;

    float4 ra[2], rb[2];
#pragma unroll
    for (int q = 0; q < 2; q++) {
        ra[q] = *reinterpret_cast<const float4*>(&A[(size_t)(m0 + lr + q * 64) * kD + lc]);
        rb[q] = *reinterpret_cast<const float4*>(&B[(size_t)(n0 + lr + q * 64) * kD + lc]);
    }

    for (int k0 = 0; k0 < kD; k0 += 16) {
#pragma unroll
        for (int q = 0; q < 2; q++) {
            As[lc + 0][lr + q * 64] = ra[q].x; As[lc + 1][lr + q * 64] = ra[q].y;
            As[lc + 2][lr + q * 64] = ra[q].z; As[lc + 3][lr + q * 64] = ra[q].w;
            Bs[lc + 0][lr + q * 64] = rb[q].x; Bs[lc + 1][lr + q * 64] = rb[q].y;
            Bs[lc + 2][lr + q * 64] = rb[q].z; Bs[lc + 3][lr + q * 64] = rb[q].w;
        }
        __syncthreads();
        if (k0 + 16 < kD) {
#pragma unroll
            for (int q = 0; q < 2; q++) {
                ra[q] = *reinterpret_cast<const float4*>(&A[(size_t)(m0 + lr + q * 64) * kD + k0 + 16 + lc]);
                rb[q] = *reinterpret_cast<const float4*>(&B[(size_t)(n0 + lr + q * 64) * kD + k0 + 16 + lc]);
            }
        }
#pragma unroll
        for (int k = 0; k < 16; k++) {
            float4 a0 = *reinterpret_cast<const float4*>(&As[k][ty * 4]);
            float4 a1 = *reinterpret_cast<const float4*>(&As[k][64 + ty * 4]);
            float4 b0 = *reinterpret_cast<const float4*>(&Bs[k][tx * 4]);
            float4 b1 = *reinterpret_cast<const float4*>(&Bs[k][64 + tx * 4]);
            uint64_t pa[4];
            pa[0] = reinterpret_cast<const uint64_t*>(&a0)[0];
            pa[1] = reinterpret_cast<const uint64_t*>(&a0)[1];
            pa[2] = reinterpret_cast<const uint64_t*>(&a1)[0];
            pa[3] = reinterpret_cast<const uint64_t*>(&a1)[1];
            float bv[8] = {b0.x, b0.y, b0.z, b0.w, b1.x, b1.y, b1.z, b1.w};
            uint64_t bb[8];
#pragma unroll
            for (int j = 0; j < 8; j++) bb[j] = f2pack(bv[j], bv[j]);
#pragma unroll
            for (int p = 0; p < 4; p++)
#pragma unroll
                for (int j = 0; j < 8; j++)
                    accp[p][j] = ffma2(pa[p], bb[j], accp[p][j]);
        }
        __syncthreads();
    }
#pragma unroll
    for (int p = 0; p < 4; p++) {
        int base = (p < 2) ? (ty * 4 + 2 * p) : (64 + ty * 4 + 2 * (p - 2));
        float lo[8], hi[8];
#pragma unroll
        for (int j = 0; j < 8; j++) f2unpack(accp[p][j], lo[j], hi[j]);
#pragma unroll
        for (int h = 0; h < 2; h++) {
            int row = m0 + base + h;
            float* vals = h ? hi : lo;
#pragma unroll
            for (int jh = 0; jh < 2; jh++) {
                int col0 = n0 + jh * 64 + tx * 4;
                float4 v;
                v.x = vals[jh * 4 + 0]; v.y = vals[jh * 4 + 1];
                v.z = vals[jh * 4 + 2]; v.w = vals[jh * 4 + 3];
                if (row >= col0 && row < col0 + 4) (&v.x)[row - col0] += 10.f;
                *reinterpret_cast<float4*>(&C[(size_t)row * kN + col0]) = v;
            }
        }
    }
}

// ---------------- kernel 2: per-row top-16 ----------------
__device__ __forceinline__ bool beats(float v1, int i1, float v2, int i2) {
    return (v1 > v2) || (v1 == v2 && i1 < i2);
}

__global__ void __launch_bounds__(256) topk_kernel(const float* __restrict__ sim)
{
    __shared__ float sv[256 * 16];
    __shared__ int   si[256 * 16];
    const int row = blockIdx.x, t = threadIdx.x;
    float tv[16]; int ti[16];
#pragma unroll
    for (int k = 0; k < 16; k++) { tv[k] = -3.402823466e38f; ti[k] = 0x7fffffff; }

    const float* rp = sim + (size_t)row * kN;
    for (int j = t; j < kN; j += 256) {
        float v = rp[j];
        if (beats(v, j, tv[15], ti[15])) {
            float cv = v; int ci = j;
#pragma unroll
            for (int k = 0; k < 16; k++) {
                if (beats(cv, ci, tv[k], ti[k])) {
                    float fv = tv[k]; int fi = ti[k];
                    tv[k] = cv; ti[k] = ci; cv = fv; ci = fi;
                }
            }
        }
    }
#pragma unroll
    for (int k = 0; k < 16; k++) { sv[t * 16 + k] = tv[k]; si[t * 16 + k] = ti[k]; }
    __syncthreads();

    for (int s = 128; s >= 1; s >>= 1) {
        if (t < s) {
            float mv[16]; int mi[16];
            int ia = 0, ib = 0;
#pragma unroll
            for (int k = 0; k < 16; k++) {
                float av = sv[t * 16 + ia], bw = sv[(t + s) * 16 + ib];
                int   ai = si[t * 16 + ia], bj = si[(t + s) * 16 + ib];
                bool ta = beats(av, ai, bw, bj);
                mv[k] = ta ? av : bw; mi[k] = ta ? ai : bj;
                if (ta) ia++; else ib++;
            }
#pragma unroll
            for (int k = 0; k < 16; k++) { sv[t * 16 + k] = mv[k]; si[t * 16 + k] = mi[k]; }
        }
        __syncthreads();
    }
    if (t < kTK) g_knn[row * kTK + t] = si[t];
}

// ---------------- kernel 3: gather init centroids ----------------
__global__ void gather_kernel(const float* __restrict__ X, IdxArr ia)
{
    int b = blockIdx.x;
    int src = ia.v[b];
    for (int d = threadIdx.x; d < kD; d += blockDim.x)
        g_cent[(size_t)b * kD + d] = X[(size_t)src * kD + d];
}

// ---------------- kernel 4: centroid norms (initial) ----------------
__global__ void __launch_bounds__(128) cnorm_kernel()
{
    int rc = blockIdx.x;
    float s = 0.f;
    for (int d = threadIdx.x; d < kD; d += 128) {
        float v = g_cent[(size_t)rc * kD + d];
        s = fmaf(v, v, s);
    }
#pragma unroll
    for (int m = 16; m >= 1; m >>= 1) s += __shfl_xor_sync(0xffffffffu, s, m);
    __shared__ float red[4];
    if ((threadIdx.x & 31) == 0) red[threadIdx.x >> 5] = s;
    __syncthreads();
    if (threadIdx.x == 0) g_cnorm[rc] = red[0] + red[1] + red[2] + red[3];
}

// ---------------- kernel 5: fused dist-GEMM + argmin (prefetch) ----------------
__global__ void __launch_bounds__(256) assign_kernel(const float* __restrict__ X)
{
    __shared__ __align__(16) float As[16][132];
    __shared__ __align__(16) float Bs[16][68];
    __shared__ float cns[kNC];

    const int r = blockIdx.y, m0 = blockIdx.x * 128;
    const float* B = g_cent + (size_t)r * kNC * kD;
    const int tid = threadIdx.x;
    const int tx = tid & 15, ty = tid >> 4;
    const int lr = tid >> 2, lc = (tid & 3) << 2;

    if (tid < kNC) cns[tid] = g_cnorm[r * kNC + tid];

    uint64_t accp[4][4];
#pragma unroll
    for (int p = 0; p < 4; p++)
#pragma unroll
        for (int j = 0; j < 4; j++) accp[p][j] = 0ull;

    float4 ra[2], rb;
#pragma unroll
    for (int q = 0; q < 2; q++)
        ra[q] = *reinterpret_cast<const float4*>(&X[(size_t)(m0 + lr + q * 64) * kD + lc]);
    rb = *reinterpret_cast<const float4*>(&B[(size_t)lr * kD + lc]);

    for (int k0 = 0; k0 < kD; k0 += 16) {
#pragma unroll
        for (int q = 0; q < 2; q++) {
            As[lc + 0][lr + q * 64] = ra[q].x; As[lc + 1][lr + q * 64] = ra[q].y;
            As[lc + 2][lr + q * 64] = ra[q].z; As[lc + 3][lr + q * 64] = ra[q].w;
        }
        Bs[lc + 0][lr] = rb.x; Bs[lc + 1][lr] = rb.y;
        Bs[lc + 2][lr] = rb.z; Bs[lc + 3][lr] = rb.w;
        __syncthreads();
        if (k0 + 16 < kD) {
#pragma unroll
            for (int q = 0; q < 2; q++)
                ra[q] = *reinterpret_cast<const float4*>(&X[(size_t)(m0 + lr + q * 64) * kD + k0 + 16 + lc]);
            rb = *reinterpret_cast<const float4*>(&B[(size_t)lr * kD + k0 + 16 + lc]);
        }
#pragma unroll
        for (int k = 0; k < 16; k++) {
            float4 a0 = *reinterpret_cast<const float4*>(&As[k][ty * 4]);
            float4 a1 = *reinterpret_cast<const float4*>(&As[k][64 + ty * 4]);
            float4 b  = *reinterpret_cast<const float4*>(&Bs[k][tx * 4]);
            uint64_t pa[4];
            pa[0] = reinterpret_cast<const uint64_t*>(&a0)[0];
            pa[1] = reinterpret_cast<const uint64_t*>(&a0)[1];
            pa[2] = reinterpret_cast<const uint64_t*>(&a1)[0];
            pa[3] = reinterpret_cast<const uint64_t*>(&a1)[1];
            float bv[4] = {b.x, b.y, b.z, b.w};
            uint64_t bb[4];
#pragma unroll
            for (int j = 0; j < 4; j++) bb[j] = f2pack(bv[j], bv[j]);
#pragma unroll
            for (int p = 0; p < 4; p++)
#pragma unroll
                for (int j = 0; j < 4; j++)
                    accp[p][j] = ffma2(pa[p], bb[j], accp[p][j]);
        }
        __syncthreads();
    }
#pragma unroll
    for (int p = 0; p < 4; p++) {
        int base = (p < 2) ? (ty * 4 + 2 * p) : (64 + ty * 4 + 2 * (p - 2));
        float lo[4], hi[4];
#pragma unroll
        for (int j = 0; j < 4; j++) f2unpack(accp[p][j], lo[j], hi[j]);
#pragma unroll
        for (int h = 0; h < 2; h++) {
            float* vals = h ? hi : lo;
            float bvm = cns[tx * 4] - 2.f * vals[0];
            int   bi  = tx * 4;
#pragma unroll
            for (int j = 1; j < 4; j++) {
                float v = cns[tx * 4 + j] - 2.f * vals[j];
                if (v < bvm) { bvm = v; bi = tx * 4 + j; }
            }
#pragma unroll
            for (int m = 1; m < 16; m <<= 1) {
                float ov = __shfl_xor_sync(0xffffffffu, bvm, m);
                int   oi = __shfl_xor_sync(0xffffffffu, bi, m);
                if (ov < bvm || (ov == bvm && oi < bi)) { bvm = ov; bi = oi; }
            }
            if (tx == 0) g_labels[r * kN + m0 + base + h] = bi;
        }
    }
}

// ---------------- kernel 6a: point-centric partial sums (d-split) ----------------
// grid (kCH, kNR*2), 256 threads; smem = 64*256 floats + 256 + 64 ints
__global__ void __launch_bounds__(256) partial_kernel(const float* __restrict__ X)
{
    extern __shared__ float sm[];
    float* ssum = sm;                            // [kNC][256]
    int*   slab = (int*)(sm + kNC * 256);        // [kCHP]
    int*   scnt = (int*)(sm + kNC * 256) + kCHP; // [kNC]

    const int ch = blockIdx.x;
    const int r  = blockIdx.y >> 1, dh = blockIdx.y & 1;
    const int t = threadIdx.x;                   // 0..255
    const int d = dh * 256 + t;
    const int p0 = ch * kCHP;
    const int* lab = g_labels + r * kN;

#pragma unroll
    for (int c = 0; c < kNC; c++) ssum[c * 256 + t] = 0.f;
    if (t < kNC) scnt[t] = 0;
    slab[t] = lab[p0 + t];
    __syncthreads();
    if (dh == 0) atomicAdd(&scnt[slab[t]], 1);
    __syncthreads();

    for (int i = 0; i < kCHP; i += 8) {
        float x0 = X[(size_t)(p0 + i + 0) * kD + d];
        float x1 = X[(size_t)(p0 + i + 1) * kD + d];
        float x2 = X[(size_t)(p0 + i + 2) * kD + d];
        float x3 = X[(size_t)(p0 + i + 3) * kD + d];
        float x4 = X[(size_t)(p0 + i + 4) * kD + d];
        float x5 = X[(size_t)(p0 + i + 5) * kD + d];
        float x6 = X[(size_t)(p0 + i + 6) * kD + d];
        float x7 = X[(size_t)(p0 + i + 7) * kD + d];
        int c0 = slab[i + 0], c1 = slab[i + 1], c2 = slab[i + 2], c3 = slab[i + 3];
        int c4 = slab[i + 4], c5 = slab[i + 5], c6 = slab[i + 6], c7 = slab[i + 7];
        ssum[c0 * 256 + t] += x0;
        ssum[c1 * 256 + t] += x1;
        ssum[c2 * 256 + t] += x2;
        ssum[c3 * 256 + t] += x3;
        ssum[c4 * 256 + t] += x4;
        ssum[c5 * 256 + t] += x5;
        ssum[c6 * 256 + t] += x6;
        ssum[c7 * 256 + t] += x7;
    }
    __syncthreads();

    const size_t base = (size_t)(r * kCH + ch) * kNC;
#pragma unroll
    for (int c = 0; c < kNC; c++)
        g_part[(base + c) * kD + d] = ssum[c * 256 + t];
    if (dh == 0 && t < kNC) g_pcnt[base + t] = scnt[t];
}

// ---------------- kernel 6b: combine partials -> centroid + norm ----------------
__global__ void __launch_bounds__(512) combine_kernel()
{
    __shared__ float fred[16];
    const int c = blockIdx.x, r = blockIdx.y;
    const int t = threadIdx.x;
    const unsigned lane = t & 31;

    int cnt = 0;
    float sum = 0.f;
#pragma unroll
    for (int ch = 0; ch < kCH; ch++) {           // fixed ascending chunk order
        size_t base = (size_t)(r * kCH + ch) * kNC + c;
        cnt += g_pcnt[base];
        sum += g_part[base * kD + t];
    }
    const int rc = r * kNC + c;
    float oldc = g_cent[(size_t)rc * kD + t];
    float newc = (cnt > 0) ? (sum / (float)cnt) : oldc;
    g_cent[(size_t)rc * kD + t] = newc;

    float sq = newc * newc;
#pragma unroll
    for (int m = 16; m >= 1; m >>= 1) sq += __shfl_xor_sync(0xffffffffu, sq, m);
    if (lane == 0) fred[t >> 5] = sq;
    __syncthreads();
    if (t == 0) {
        float s = 0.f;
        for (int w = 0; w < 16; w++) s += fred[w];
        g_cnorm[rc] = s;
    }
}

// ---------------- kernel 7: scatter final output ----------------
__global__ void __launch_bounds__(256) scatter_kernel(
    const float* __restrict__ adj, float* __restrict__ out)
{
    int e = blockIdx.x * blockDim.x + threadIdx.x;
    int i = e >> 4;
    int j = g_knn[e];
    float v = adj[(size_t)i * kN + j];
    bool m = false;
#pragma unroll
    for (int r = 0; r < kNR; r++)
        m |= (g_labels[r * kN + i] == g_labels[r * kN + j]);
    out[(size_t)i * kN + j] = v + (m ? 1.f : 0.f);
}

// ---------------- launcher: two-stream overlap ----------------
extern "C" void kernel_launch(void* const* d_in, const int* in_sizes, int n_in,
                              void* d_out, int out_size)
{
    (void)in_sizes; (void)n_in; (void)out_size;
    const float* adj     = (const float*)d_in[0];
    const float* student = (const float*)d_in[1];
    const float* teacher = (const float*)d_in[2];
    float* out = (float*)d_out;

    constexpr size_t kPartSmem = (size_t)kNC * 256 * 4 + kCHP * 4 + kNC * 4; // ~66.8 KB
    static cudaStream_t s2 = nullptr;
    static cudaEvent_t ev_fork = nullptr, ev_join = nullptr;
    if (!s2) {
        cudaStreamCreateWithFlags(&s2, cudaStreamNonBlocking);
        cudaEventCreateWithFlags(&ev_fork, cudaEventDisableTiming);
        cudaEventCreateWithFlags(&ev_join, cudaEventDisableTiming);
        cudaFuncSetAttribute(partial_kernel,
                             cudaFuncAttributeMaxDynamicSharedMemorySize, (int)kPartSmem);
    }

    IdxArr ia;
    compute_init_indices(ia.v);

    // fork: kmeans chain (teacher only) on s2
    cudaEventRecord(ev_fork, 0);
    cudaStreamWaitEvent(s2, ev_fork, 0);

    gather_kernel<<<kRC, 128, 0, s2>>>(teacher, ia);
    cnorm_kernel<<<kRC, 128, 0, s2>>>();
    dim3 ga(kN / 128, kNR), gp(kCH, kNR * 2), gc(kNC, kNR);
    for (int it = 0; it < kIters; it++) {
        assign_kernel<<<ga, 256, 0, s2>>>(teacher);
        partial_kernel<<<gp, 256, kPartSmem, s2>>>(teacher);
        combine_kernel<<<gc, 512, 0, s2>>>();
    }
    assign_kernel<<<ga, 256, 0, s2>>>(teacher);
    cudaEventRecord(ev_join, s2);

    // main stream: sim GEMM -> topk -> zero out
    dim3 g1(kN / 128, kN / 128);
    gemm_sim_kernel<<<g1, 256>>>(student, teacher, out);
    topk_kernel<<<kN, 256>>>(out);
    cudaMemsetAsync(d_out, 0, (size_t)kN * kN * sizeof(float), 0);

    // join + scatter
    cudaStreamWaitEvent(0, ev_join, 0);
    scatter_kernel<<<kN * kTK / 256, 256>>>(adj, out);
}